// round 16
// baseline (speedup 1.0000x reference)
#include <cuda_runtime.h>
#include <cuda_fp16.h>
#include <cstdint>

// ---------------- Problem constants ----------------
#define NCTX   65536
#define BATCH  2048
#define LMAX   48

// ---------------- low-level helpers ----------------
__device__ __forceinline__ uint32_t smem_u32(const void* p) {
    uint32_t a;
    asm("{ .reg .u64 t; cvta.to.shared.u64 t, %1; cvt.u32.u64 %0, t; }" : "=r"(a) : "l"(p));
    return a;
}
__device__ __forceinline__ void cp16(uint32_t s, const void* g) {
    asm volatile("cp.async.cg.shared.global [%0], [%1], 16;" :: "r"(s), "l"(g));
}
__device__ __forceinline__ void cp_commit() {
    asm volatile("cp.async.commit_group;" ::: "memory");
}
__device__ __forceinline__ void cp_wait1() {
    asm volatile("cp.async.wait_group 1;" ::: "memory");
}
__device__ __forceinline__ void cp_wait0() {
    asm volatile("cp.async.wait_group 0;" ::: "memory");
}
__device__ __forceinline__ void ldsm4(uint32_t& r0, uint32_t& r1, uint32_t& r2, uint32_t& r3,
                                      uint32_t addr) {
    asm volatile("ldmatrix.sync.aligned.m8n8.x4.shared.b16 {%0,%1,%2,%3}, [%4];"
                 : "=r"(r0), "=r"(r1), "=r"(r2), "=r"(r3) : "r"(addr));
}
__device__ __forceinline__ void mma16816(float* c, uint32_t a0, uint32_t a1, uint32_t a2,
                                         uint32_t a3, uint32_t b0, uint32_t b1) {
    asm volatile(
        "mma.sync.aligned.m16n8k16.row.col.f32.f16.f16.f32 "
        "{%0,%1,%2,%3}, {%4,%5,%6,%7}, {%8,%9}, {%0,%1,%2,%3};"
        : "+f"(c[0]), "+f"(c[1]), "+f"(c[2]), "+f"(c[3])
        : "r"(a0), "r"(a1), "r"(a2), "r"(a3), "r"(b0), "r"(b1));
}

// ---------------- Scratch (static device globals) ----------------
__device__ __half g_a1[NCTX * 512];
__device__ __half g_a2[NCTX * 512];
__device__ float  g_qpp[NCTX * 512];           // q'' = a2 @ M + r
__device__ __half g_ctx[BATCH * 512];          // attention context vectors
__device__ __half g_dcat[2 * BATCH * 1536];
__device__ __half g_d1[2 * BATCH * 512];
// fp16 transposed weights Wt[n][k]
__device__ __half g_w1t[512 * 2048];
__device__ __half g_w2t[512 * 512];
__device__ __half g_Mt[512 * 512];             // Mt[n][k] = (C1@C2^T)[k][n]
__device__ __half g_wmct[1024 * 512];          // (C3@[wm|wlv])^T blocks
__device__ __half g_dw1t[512 * 1536];
__device__ __half g_dw2t[512 * 512];
// fp32 composition scratch
__device__ float g_C1[512 * 512], g_C2[512 * 512], g_C3[512 * 512];
__device__ float g_bc[1536];                   // bqc | bkc | bvc
__device__ float g_r[512];                     // C2 @ bqc
__device__ float g_bh2[1024];                  // composed head bias
__device__ float g_d2[2 * BATCH * 512];

// ---------------- generic HMMA GEMM (fp16 single-pass, 3-stage) ----------------
// OUTMODE: 0 = fp16 (ldc), 1 = fp32 (ldc), 2 = heads split fp32 (N=1024 -> two blocks)
#define STG_BYTES 20480u
#define GEMM_DSM  (3 * 20480)

template <int ACT, int OUTMODE>
__global__ void __launch_bounds__(256, 2)
gemm_mma(const __half* __restrict__ Ah, int K,
         const __half* __restrict__ Bt,
         const float* __restrict__ bias, int ldc,
         float* __restrict__ outF, __half* __restrict__ outH)
{
    extern __shared__ char dsm[];
    const uint32_t smBase = smem_u32(dsm);

    const int tid = threadIdx.x;
    const int lane = tid & 31;
    const int w = tid >> 5;
    const int warp_m = w >> 2;
    const int warp_n = w & 3;
    const int m0 = blockIdx.y * 128;
    const int n0 = blockIdx.x * 128;

    float c[4][4][4];
#pragma unroll
    for (int mi = 0; mi < 4; mi++)
#pragma unroll
        for (int ni = 0; ni < 4; ni++)
#pragma unroll
            for (int r = 0; r < 4; r++) c[mi][ni][r] = 0.f;

    const int nk = K >> 5;

    auto load_stage = [&](int s) {
        const uint32_t sb = smBase + (uint32_t)(s % 3) * STG_BYTES;
        const int k0 = s << 5;
#pragma unroll
        for (int j = 0; j < 2; j++) {
            int slot = tid + j * 256;
            int row = slot >> 2, k8 = slot & 3;
            uint32_t dst = sb + (uint32_t)row * 80u + (uint32_t)k8 * 16u;
            cp16(dst,           Ah + (size_t)(m0 + row) * K + k0 + k8 * 8);
            cp16(dst + 10240u,  Bt + (size_t)(n0 + row) * K + k0 + k8 * 8);
        }
    };

    load_stage(0); cp_commit();
    load_stage(1); cp_commit();

    const int lr = lane & 15;
    const uint32_t lc16 = (uint32_t)(lane >> 4) * 16u;

    for (int s = 0; s < nk; s++) {
        cp_wait1();
        __syncthreads();
        if (s + 2 < nk) load_stage(s + 2);
        cp_commit();

        const uint32_t sb = smBase + (uint32_t)(s % 3) * STG_BYTES;
#pragma unroll
        for (int h = 0; h < 2; h++) {
            const uint32_t koff = (uint32_t)h * 32u + lc16;
            uint32_t aa[4][4], bb[2][4];
#pragma unroll
            for (int mi = 0; mi < 4; mi++) {
                uint32_t addr = sb + (uint32_t)((warp_m * 64 + mi * 16 + lr) * 80) + koff;
                ldsm4(aa[mi][0], aa[mi][1], aa[mi][2], aa[mi][3], addr);
            }
#pragma unroll
            for (int bt = 0; bt < 2; bt++) {
                uint32_t addr = sb + 10240u + (uint32_t)((warp_n * 32 + bt * 16 + lr) * 80) + koff;
                ldsm4(bb[bt][0], bb[bt][1], bb[bt][2], bb[bt][3], addr);
            }
#pragma unroll
            for (int ni = 0; ni < 4; ni++) {
                const int bt = ni >> 1, sl = ni & 1;
#pragma unroll
                for (int mi = 0; mi < 4; mi++)
                    mma16816(c[mi][ni], aa[mi][0], aa[mi][1], aa[mi][2], aa[mi][3],
                             bb[bt][sl], bb[bt][sl + 2]);
            }
        }
    }

#pragma unroll
    for (int mi = 0; mi < 4; mi++) {
        const int row = m0 + warp_m * 64 + mi * 16 + (lane >> 2);
#pragma unroll
        for (int ni = 0; ni < 4; ni++) {
            const int col = n0 + warp_n * 32 + ni * 8 + (lane & 3) * 2;
            const float b0 = bias[col], b1 = bias[col + 1];
            float v0 = c[mi][ni][0] + b0, v1 = c[mi][ni][1] + b1;
            float v2 = c[mi][ni][2] + b0, v3 = c[mi][ni][3] + b1;
            if (ACT == 1) {
                v0 = v0 > 0.f ? v0 : 0.2f * v0;
                v1 = v1 > 0.f ? v1 : 0.2f * v1;
                v2 = v2 > 0.f ? v2 : 0.2f * v2;
                v3 = v3 > 0.f ? v3 : 0.2f * v3;
            } else if (ACT == 2) {
                v0 = fminf(fmaxf(v0, -1.f), 1.f);
                v1 = fminf(fmaxf(v1, -1.f), 1.f);
                v2 = fminf(fmaxf(v2, -1.f), 1.f);
                v3 = fminf(fmaxf(v3, -1.f), 1.f);
            }
            if (OUTMODE == 1) {
                *(float2*)(outF + (size_t)row * ldc + col)       = make_float2(v0, v1);
                *(float2*)(outF + (size_t)(row + 8) * ldc + col) = make_float2(v2, v3);
            } else if (OUTMODE == 2) {
                size_t base = (size_t)(col >> 9) * ((size_t)BATCH * 512) + (col & 511);
                *(float2*)(outF + base + (size_t)row * 512)       = make_float2(v0, v1);
                *(float2*)(outF + base + (size_t)(row + 8) * 512) = make_float2(v2, v3);
            } else {
                *(__half2*)(outH + (size_t)row * ldc + col) =
                    __halves2half2(__float2half_rn(v0), __float2half_rn(v1));
                *(__half2*)(outH + (size_t)(row + 8) * ldc + col) =
                    __halves2half2(__float2half_rn(v2), __float2half_rn(v3));
            }
        }
    }
}

// ---------------- layer-1 GEMM with fused fp32->fp16 conversion ----------------
#define L1_STG 36864u
#define L1_DSM (2 * 36864)

__global__ void __launch_bounds__(256, 2)
gemm_l1(const float* __restrict__ cc, const float* __restrict__ cr,
        const __half* __restrict__ Bt, const float* __restrict__ bias,
        __half* __restrict__ outH)
{
    extern __shared__ char dsm[];
    const uint32_t smBase = smem_u32(dsm);
    const int K = 2048, nk = 64;

    const int tid = threadIdx.x;
    const int lane = tid & 31;
    const int w = tid >> 5;
    const int warp_m = w >> 2;
    const int warp_n = w & 3;
    const int m0 = blockIdx.y * 128;
    const int n0 = blockIdx.x * 128;

    float c[4][4][4];
#pragma unroll
    for (int mi = 0; mi < 4; mi++)
#pragma unroll
        for (int ni = 0; ni < 4; ni++)
#pragma unroll
            for (int r = 0; r < 4; r++) c[mi][ni][r] = 0.f;

    auto load_stage = [&](int s) {
        const uint32_t sb = smBase + (uint32_t)(s & 1) * L1_STG;
        const int k0 = s << 5;
        const float* A = (k0 < 1024) ? cc : cr;
        const int kc = k0 & 1023;
#pragma unroll
        for (int j = 0; j < 4; j++) {
            int slot = tid + j * 256;
            int row = slot >> 3, c8 = slot & 7;
            cp16(sb + (uint32_t)row * 128u + (uint32_t)c8 * 16u,
                 A + (size_t)(m0 + row) * 1024 + kc + c8 * 4);
        }
#pragma unroll
        for (int j = 0; j < 2; j++) {
            int slot = tid + j * 256;
            int row = slot >> 2, k8 = slot & 3;
            cp16(sb + 26624u + (uint32_t)row * 80u + (uint32_t)k8 * 16u,
                 Bt + (size_t)(n0 + row) * 2048 + k0 + k8 * 8);
        }
    };

    load_stage(0); cp_commit();

    const int lr = lane & 15;
    const uint32_t lc16 = (uint32_t)(lane >> 4) * 16u;

    for (int s = 0; s < nk; s++) {
        cp_wait0();
        __syncthreads();
        if (s + 1 < nk) { load_stage(s + 1); cp_commit(); }

        const uint32_t sb = smBase + (uint32_t)(s & 1) * L1_STG;

#pragma unroll
        for (int j = 0; j < 4; j++) {
            int slot = tid + j * 256;
            int row = slot >> 3, c8 = slot & 7;
            float4 v = *(const float4*)(dsm + (size_t)((s & 1) * L1_STG) + row * 128 + c8 * 16);
            char* hp = dsm + (size_t)((s & 1) * L1_STG) + 16384 + row * 80 + c8 * 8;
            *(__half2*)(hp)     = __halves2half2(__float2half_rn(v.x), __float2half_rn(v.y));
            *(__half2*)(hp + 4) = __halves2half2(__float2half_rn(v.z), __float2half_rn(v.w));
        }
        __syncthreads();

#pragma unroll
        for (int h = 0; h < 2; h++) {
            const uint32_t koff = (uint32_t)h * 32u + lc16;
            uint32_t aa[4][4], bb[2][4];
#pragma unroll
            for (int mi = 0; mi < 4; mi++) {
                uint32_t addr = sb + 16384u + (uint32_t)((warp_m * 64 + mi * 16 + lr) * 80) + koff;
                ldsm4(aa[mi][0], aa[mi][1], aa[mi][2], aa[mi][3], addr);
            }
#pragma unroll
            for (int bt = 0; bt < 2; bt++) {
                uint32_t addr = sb + 26624u + (uint32_t)((warp_n * 32 + bt * 16 + lr) * 80) + koff;
                ldsm4(bb[bt][0], bb[bt][1], bb[bt][2], bb[bt][3], addr);
            }
#pragma unroll
            for (int ni = 0; ni < 4; ni++) {
                const int bt = ni >> 1, sl = ni & 1;
#pragma unroll
                for (int mi = 0; mi < 4; mi++)
                    mma16816(c[mi][ni], aa[mi][0], aa[mi][1], aa[mi][2], aa[mi][3],
                             bb[bt][sl], bb[bt][sl + 2]);
            }
        }
    }

#pragma unroll
    for (int mi = 0; mi < 4; mi++) {
        const int row = m0 + warp_m * 64 + mi * 16 + (lane >> 2);
#pragma unroll
        for (int ni = 0; ni < 4; ni++) {
            const int col = n0 + warp_n * 32 + ni * 8 + (lane & 3) * 2;
            const float b0 = bias[col], b1 = bias[col + 1];
            float v0 = c[mi][ni][0] + b0, v1 = c[mi][ni][1] + b1;
            float v2 = c[mi][ni][2] + b0, v3 = c[mi][ni][3] + b1;
            v0 = v0 > 0.f ? v0 : 0.2f * v0;
            v1 = v1 > 0.f ? v1 : 0.2f * v1;
            v2 = v2 > 0.f ? v2 : 0.2f * v2;
            v3 = v3 > 0.f ? v3 : 0.2f * v3;
            *(__half2*)(outH + (size_t)row * 512 + col) =
                __halves2half2(__float2half_rn(v0), __float2half_rn(v1));
            *(__half2*)(outH + (size_t)(row + 8) * 512 + col) =
                __halves2half2(__float2half_rn(v2), __float2half_rn(v3));
        }
    }
}

// ---------------- fp32 -> fp16 (strided into concat buffer) ----------------
__global__ void __launch_bounds__(256)
conv_h(const float* __restrict__ src, int total4, int kshift, int kmask,
       int dstStride, int dstOff, __half* __restrict__ h)
{
    int i = blockIdx.x * 256 + threadIdx.x;
    if (i >= total4) return;
    int e = i << 2;
    int row = e >> kshift, col = e & kmask;
    float4 v = *(const float4*)(src + e);
    size_t o = (size_t)row * dstStride + dstOff + col;
    __half2* hp = (__half2*)(h + o);
    hp[0] = __halves2half2(__float2half_rn(v.x), __float2half_rn(v.y));
    hp[1] = __halves2half2(__float2half_rn(v.z), __float2half_rn(v.w));
}

// ---------------- weight transpose + fp16: W[K,512] -> Wt[512,K] ----------------
__global__ void __launch_bounds__(256)
wt_conv(const float* __restrict__ W, int K, __half* __restrict__ T)
{
    __shared__ float t[32][33];
    const int nb = blockIdx.x * 32, kb = blockIdx.y * 32;
    const int tx = threadIdx.x & 31, ty = threadIdx.x >> 5;
#pragma unroll
    for (int i = 0; i < 32; i += 8)
        t[ty + i][tx] = W[(size_t)(kb + ty + i) * 512 + nb + tx];
    __syncthreads();
#pragma unroll
    for (int i = 0; i < 32; i += 8)
        T[(size_t)(nb + ty + i) * K + kb + tx] = __float2half_rn(t[tx][ty + i]);
}

// ---------------- compose C = A@B fp32, row-major out ----------------
__global__ void __launch_bounds__(256)
compose_f32(const float* __restrict__ A, const float* __restrict__ B, float* __restrict__ C)
{
    __shared__ float As[64][17];
    __shared__ float Bs[16][68];
    const int i0 = blockIdx.y * 64, nb0 = blockIdx.x * 64;
    const int tx = threadIdx.x & 15, ty = threadIdx.x >> 4;
    float acc[4][4] = {};
    for (int j0 = 0; j0 < 512; j0 += 16) {
        for (int t = threadIdx.x; t < 1024; t += 256) {
            int r = t >> 4, jj = t & 15;
            As[r][jj] = A[(size_t)(i0 + r) * 512 + j0 + jj];
        }
        for (int t = threadIdx.x; t < 1024; t += 256) {
            int r = t >> 6, nn = t & 63;
            Bs[r][nn] = B[(size_t)(j0 + r) * 512 + nb0 + nn];
        }
        __syncthreads();
#pragma unroll
        for (int jj = 0; jj < 16; jj++) {
            float a[4], b[4];
#pragma unroll
            for (int u = 0; u < 4; u++) a[u] = As[ty * 4 + u][jj];
#pragma unroll
            for (int u = 0; u < 4; u++) b[u] = Bs[jj][tx * 4 + u];
#pragma unroll
            for (int u = 0; u < 4; u++)
#pragma unroll
                for (int v = 0; v < 4; v++) acc[u][v] += a[u] * b[v];
        }
        __syncthreads();
    }
#pragma unroll
    for (int u = 0; u < 4; u++)
#pragma unroll
        for (int v = 0; v < 4; v++)
            C[(size_t)(i0 + ty * 4 + u) * 512 + nb0 + tx * 4 + v] = acc[u][v];
}

// ---------------- compose T[n][k] = sum_j A[k][j]*B[n][j], fp16 out ----------------
__global__ void __launch_bounds__(256)
compose_nt(const float* __restrict__ A, const float* __restrict__ B, __half* __restrict__ T)
{
    __shared__ float As[64][17];   // rows k
    __shared__ float Bs[64][17];   // rows n
    const int k0 = blockIdx.y * 64, n0 = blockIdx.x * 64;
    const int tx = threadIdx.x & 15, ty = threadIdx.x >> 4;
    float acc[4][4] = {};          // acc[u][v]: k = k0+ty*4+u, n = n0+tx*4+v
    for (int j0 = 0; j0 < 512; j0 += 16) {
        for (int t = threadIdx.x; t < 1024; t += 256) {
            int r = t >> 4, jj = t & 15;
            As[r][jj] = A[(size_t)(k0 + r) * 512 + j0 + jj];
            Bs[r][jj] = B[(size_t)(n0 + r) * 512 + j0 + jj];
        }
        __syncthreads();
#pragma unroll
        for (int jj = 0; jj < 16; jj++) {
            float a[4], b[4];
#pragma unroll
            for (int u = 0; u < 4; u++) a[u] = As[ty * 4 + u][jj];
#pragma unroll
            for (int u = 0; u < 4; u++) b[u] = Bs[tx * 4 + u][jj];
#pragma unroll
            for (int u = 0; u < 4; u++)
#pragma unroll
                for (int v = 0; v < 4; v++) acc[u][v] += a[u] * b[v];
        }
        __syncthreads();
    }
#pragma unroll
    for (int u = 0; u < 4; u++)
#pragma unroll
        for (int v = 0; v < 4; v++)
            T[(size_t)(n0 + tx * 4 + v) * 512 + k0 + ty * 4 + u] = __float2half_rn(acc[u][v]);
}

// ---------------- compose T[n][k] = (A@B)[k][n] fp16 (A fp32 512x512, B fp32 512x512) ----------------
__global__ void __launch_bounds__(256)
compose_w(const float* __restrict__ A, const float* __restrict__ B, __half* __restrict__ T)
{
    __shared__ float As[64][17];
    __shared__ float Bs[16][68];
    const int i0 = blockIdx.y * 64, nb0 = blockIdx.x * 64;
    const int tx = threadIdx.x & 15, ty = threadIdx.x >> 4;
    float acc[4][4] = {};
    for (int j0 = 0; j0 < 512; j0 += 16) {
        for (int t = threadIdx.x; t < 1024; t += 256) {
            int r = t >> 4, jj = t & 15;
            As[r][jj] = A[(size_t)(i0 + r) * 512 + j0 + jj];
        }
        for (int t = threadIdx.x; t < 1024; t += 256) {
            int r = t >> 6, nn = t & 63;
            Bs[r][nn] = B[(size_t)(j0 + r) * 512 + nb0 + nn];
        }
        __syncthreads();
#pragma unroll
        for (int jj = 0; jj < 16; jj++) {
            float a[4], b[4];
#pragma unroll
            for (int u = 0; u < 4; u++) a[u] = As[ty * 4 + u][jj];
#pragma unroll
            for (int u = 0; u < 4; u++) b[u] = Bs[jj][tx * 4 + u];
#pragma unroll
            for (int u = 0; u < 4; u++)
#pragma unroll
                for (int v = 0; v < 4; v++) acc[u][v] += a[u] * b[v];
        }
        __syncthreads();
    }
#pragma unroll
    for (int u = 0; u < 4; u++)
#pragma unroll
        for (int v = 0; v < 4; v++) {
            int i = i0 + ty * 4 + u, n = nb0 + tx * 4 + v;
            T[(size_t)n * 512 + i] = __float2half_rn(acc[u][v]);
        }
}

// ---------------- composed projection biases bqc|bkc|bvc ----------------
__global__ void __launch_bounds__(512)
compose_bias(const float* __restrict__ b3,
             const float* __restrict__ Bq, const float* __restrict__ Bk, const float* __restrict__ Bv,
             const float* __restrict__ bq, const float* __restrict__ bk, const float* __restrict__ bv,
             float* __restrict__ bc)
{
    const int seg = blockIdx.x, n = threadIdx.x;
    const float* B = seg == 0 ? Bq : seg == 1 ? Bk : Bv;
    const float* bb = seg == 0 ? bq : seg == 1 ? bk : bv;
    float s = bb[n];
    for (int j = 0; j < 512; j++) s += b3[j] * B[(size_t)j * 512 + n];
    bc[seg * 512 + n] = s;
}

// ---------------- r = C2 @ bqc ----------------
__global__ void __launch_bounds__(512)
r_bias(const float* __restrict__ C2, const float* __restrict__ bqc, float* __restrict__ r)
{
    const int n = threadIdx.x;
    float s = 0.f;
    for (int j = 0; j < 512; j++) s += C2[(size_t)n * 512 + j] * bqc[j];
    r[n] = s;
}

// ---------------- head bias: bh2[seg*512+n] = bvc . wh[:,n] + bh[n] ----------------
__global__ void __launch_bounds__(512)
hb_compose(const float* __restrict__ bvc,
           const float* __restrict__ Wm, const float* __restrict__ Wlv,
           const float* __restrict__ bm, const float* __restrict__ blv,
           float* __restrict__ bh2)
{
    const int seg = blockIdx.x, n = threadIdx.x;
    const float* B = seg == 0 ? Wm : Wlv;
    const float* bb = seg == 0 ? bm : blv;
    float s = bb[n];
    for (int j = 0; j < 512; j++) s += bvc[j] * B[(size_t)j * 512 + n];
    bh2[seg * 512 + n] = s;
}

// ---------------- Attention: scores = q''.a2, ctx = colsum-weighted a2 ----------------
#define ATT_DSM (LMAX * 512 * 2)   // 49152: a2 tile fp16

__global__ void __launch_bounds__(256, 3)
attn_kernel(const float* __restrict__ qpp, const __half* __restrict__ a2,
            const int* __restrict__ sse, __half* __restrict__ ctx)
{
    extern __shared__ __half a2s[];          // [len][512] fp16
    __shared__ float scores[LMAX][LMAX];
    __shared__ float colsum[LMAX];

    const int b = blockIdx.x;
    const int tid = threadIdx.x;
    const int warp = tid >> 5, lane = tid & 31;
    const int start = sse[2 * b];
    const int len = sse[2 * b + 1] - start;

    // stage a2 segment (fp16)
    {
        const uint4* g = (const uint4*)(a2 + (size_t)start * 512);
        uint4* s4 = (uint4*)a2s;
        int tot = len * 64;
        for (int i = tid; i < tot; i += 256) s4[i] = g[i];
    }
    __syncthreads();

    // scores[l][m] = q''_l . a2_m (warp per l-row, q'' in registers)
    {
        const float scale = 0.044194173824159216f;
        const __half2* k2 = (const __half2*)a2s;
        for (int l = warp; l < len; l += 8) {
            float2 q[8];
            const float2* qr = (const float2*)(qpp + (size_t)(start + l) * 512) + lane;
#pragma unroll
            for (int i = 0; i < 8; i++) q[i] = __ldg(qr + i * 32);
            for (int m = 0; m < len; m++) {
                const __half2* kr = k2 + m * 256 + lane;
                float s = 0.f;
#pragma unroll
                for (int i = 0; i < 8; i++) {
                    float2 kv = __half22float2(kr[i * 32]);
                    s += q[i].x * kv.x + q[i].y * kv.y;
                }
#pragma unroll
                for (int off = 16; off > 0; off >>= 1)
                    s += __shfl_xor_sync(0xffffffffu, s, off);
                if (lane == 0) scores[l][m] = s * scale;
            }
        }
    }
    __syncthreads();

    if (tid < len) {
        float mx = -1e30f;
        for (int m = 0; m < len; m++) mx = fmaxf(mx, scores[tid][m]);
        float sum = 0.f;
        for (int m = 0; m < len; m++) {
            float e = __expf(scores[tid][m] - mx);
            scores[tid][m] = e; sum += e;
        }
        float inv = 1.f / sum;
        for (int m = 0; m < len; m++) scores[tid][m] *= inv;
    }
    __syncthreads();

    if (tid < len) {
        float cs = 0.f;
        for (int l = 0; l < len; l++) cs += scores[l][tid];
        colsum[tid] = cs / (float)len;
    }
    __syncthreads();

    for (int d = tid; d < 512; d += 256) {
        float s = 0.f;
        for (int m = 0; m < len; m++)
            s += colsum[m] * __half2float(a2s[m * 512 + d]);
        ctx[(size_t)b * 512 + d] = __float2half_rn(s);
    }
}

// ---------------- z: writes out_z + decoder concat z cols ----------------
__global__ void __launch_bounds__(256)
z_kernel(const float* __restrict__ mean, const float* __restrict__ lv,
         const float* __restrict__ eps, float* __restrict__ zout,
         __half* __restrict__ dcat)
{
    __shared__ float red[256];
    const int b = blockIdx.x, tid = threadIdx.x;
    float zi[2];
    float ss = 0.f;
#pragma unroll
    for (int j = 0; j < 2; j++) {
        int d = tid + 256 * j;
        size_t idx = (size_t)b * 512 + d;
        float z = mean[idx] + __expf(0.5f * lv[idx]) * eps[idx];
        zi[j] = z; ss += z * z;
    }
    red[tid] = ss;
    __syncthreads();
    for (int s = 128; s > 0; s >>= 1) {
        if (tid < s) red[tid] += red[tid + s];
        __syncthreads();
    }
    float denom = fmaxf(sqrtf(red[0]), 1e-12f);
    float fac = 22.627416997969522f / denom;
#pragma unroll
    for (int j = 0; j < 2; j++) {
        int d = tid + 256 * j;
        float z = zi[j] * fac;
        zout[(size_t)b * 512 + d] = z;
        __half h = __float2half_rn(z);
        size_t o0 = (size_t)b * 1536 + 1024 + d;
        dcat[o0] = h;
        dcat[o0 + (size_t)BATCH * 1536] = h;
    }
}

// ---------------- final head matvec (4096 rows -> contiguous out) ----------------
__global__ void __launch_bounds__(256)
matvec_kernel(const float* __restrict__ A, const float* __restrict__ w,
              const float* __restrict__ b, float* __restrict__ out)
{
    const int lane = threadIdx.x;
    const int row = blockIdx.x * 8 + threadIdx.y;
    float s = 0.f;
    for (int k = lane; k < 512; k += 32)
        s += A[(size_t)row * 512 + k] * w[k];
#pragma unroll
    for (int off = 16; off > 0; off >>= 1)
        s += __shfl_xor_sync(0xffffffffu, s, off);
    if (lane == 0) out[row] = s + b[0];
}

// ---------------- host side ----------------
extern "C" void kernel_launch(void* const* d_in, const int* in_sizes, int n_in,
                              void* d_out, int out_size)
{
    const float* tc    = (const float*)d_in[0];
    const float* tr    = (const float*)d_in[1];
    const float* cc    = (const float*)d_in[2];
    const float* cr    = (const float*)d_in[3];
    const float* eps   = (const float*)d_in[4];
    const float* pe_w1 = (const float*)d_in[5];
    const float* pe_b1 = (const float*)d_in[6];
    const float* pe_w2 = (const float*)d_in[7];
    const float* pe_b2 = (const float*)d_in[8];
    const float* pe_w3 = (const float*)d_in[9];
    const float* pe_b3 = (const float*)d_in[10];
    const float* wq    = (const float*)d_in[11];
    const float* bq    = (const float*)d_in[12];
    const float* wk    = (const float*)d_in[13];
    const float* bk    = (const float*)d_in[14];
    const float* wv    = (const float*)d_in[15];
    const float* bv    = (const float*)d_in[16];
    const float* wm    = (const float*)d_in[17];
    const float* bm    = (const float*)d_in[18];
    const float* wlv   = (const float*)d_in[19];
    const float* blv   = (const float*)d_in[20];
    const float* d_w1  = (const float*)d_in[21];
    const float* d_b1  = (const float*)d_in[22];
    const float* d_w2  = (const float*)d_in[23];
    const float* d_b2  = (const float*)d_in[24];
    const float* d_w3  = (const float*)d_in[25];
    const float* d_b3  = (const float*)d_in[26];
    const int*   sse   = (const int*)d_in[27];

    float* out = (float*)d_out;
    float* out_rc   = out;
    float* out_mean = out + 2 * BATCH;
    float* out_lv   = out_mean + BATCH * 512;
    float* out_z    = out_lv + BATCH * 512;

    __half *a1, *a2, *ctxb, *dcat, *d1;
    __half *w1t, *w2t, *Mt, *wmct, *dw1t, *dw2t;
    float *qpp, *C1, *C2, *C3, *bc, *rr, *bh2, *d2f;
    cudaGetSymbolAddress((void**)&a1, g_a1);
    cudaGetSymbolAddress((void**)&a2, g_a2);
    cudaGetSymbolAddress((void**)&ctxb, g_ctx);
    cudaGetSymbolAddress((void**)&dcat, g_dcat);
    cudaGetSymbolAddress((void**)&d1, g_d1);
    cudaGetSymbolAddress((void**)&w1t, g_w1t);
    cudaGetSymbolAddress((void**)&w2t, g_w2t);
    cudaGetSymbolAddress((void**)&Mt, g_Mt);
    cudaGetSymbolAddress((void**)&wmct, g_wmct);
    cudaGetSymbolAddress((void**)&dw1t, g_dw1t);
    cudaGetSymbolAddress((void**)&dw2t, g_dw2t);
    cudaGetSymbolAddress((void**)&qpp, g_qpp);
    cudaGetSymbolAddress((void**)&C1, g_C1);
    cudaGetSymbolAddress((void**)&C2, g_C2);
    cudaGetSymbolAddress((void**)&C3, g_C3);
    cudaGetSymbolAddress((void**)&bc, g_bc);
    cudaGetSymbolAddress((void**)&rr, g_r);
    cudaGetSymbolAddress((void**)&bh2, g_bh2);
    cudaGetSymbolAddress((void**)&d2f, g_d2);

    cudaFuncSetAttribute(gemm_l1, cudaFuncAttributeMaxDynamicSharedMemorySize, L1_DSM);
    cudaFuncSetAttribute(gemm_mma<0, 1>, cudaFuncAttributeMaxDynamicSharedMemorySize, GEMM_DSM);
    cudaFuncSetAttribute(gemm_mma<1, 0>, cudaFuncAttributeMaxDynamicSharedMemorySize, GEMM_DSM);
    cudaFuncSetAttribute(gemm_mma<1, 1>, cudaFuncAttributeMaxDynamicSharedMemorySize, GEMM_DSM);
    cudaFuncSetAttribute(gemm_mma<2, 2>, cudaFuncAttributeMaxDynamicSharedMemorySize, GEMM_DSM);
    cudaFuncSetAttribute(attn_kernel, cudaFuncAttributeMaxDynamicSharedMemorySize, ATT_DSM);

    // encoder layers 1-2
    wt_conv<<<dim3(16, 64), 256>>>(pe_w1, 2048, w1t);
    gemm_l1<<<dim3(4, NCTX / 128), 256, L1_DSM>>>(cc, cr, w1t, pe_b1, a1);
    wt_conv<<<dim3(16, 16), 256>>>(pe_w2, 512, w2t);
    gemm_mma<1, 0><<<dim3(4, NCTX / 128), 256, GEMM_DSM>>>(a1, 512, w2t, pe_b2, 512, nullptr, a2);

    // compositions: C1=pe_w3@wq, C2=pe_w3@wk, C3=pe_w3@wv
    compose_f32<<<dim3(8, 8), 256>>>(pe_w3, wq, C1);
    compose_f32<<<dim3(8, 8), 256>>>(pe_w3, wk, C2);
    compose_f32<<<dim3(8, 8), 256>>>(pe_w3, wv, C3);
    compose_bias<<<3, 512>>>(pe_b3, wq, wk, wv, bq, bk, bv, bc);
    compose_nt<<<dim3(8, 8), 256>>>(C1, C2, Mt);       // Mt[n][k] = (C1@C2^T)[k][n]
    r_bias<<<1, 512>>>(C2, bc, rr);                    // r = C2 @ bqc

    // q'' = a2 @ M + r (fp32 out)
    gemm_mma<0, 1><<<dim3(4, NCTX / 128), 256, GEMM_DSM>>>(a2, 512, Mt, rr, 512, qpp, nullptr);

    // attention -> ctx (fp16)
    attn_kernel<<<BATCH, 256, ATT_DSM>>>(qpp, a2, sse, ctxb);

    // heads: ctx @ (C3@[wm|wlv]) + composed bias -> mean|lv
    compose_w<<<dim3(8, 8), 256>>>(C3, wm, wmct);
    compose_w<<<dim3(8, 8), 256>>>(C3, wlv, wmct + (size_t)512 * 512);
    hb_compose<<<2, 512>>>(bc + 1024, wm, wlv, bm, blv, bh2);
    gemm_mma<2, 2><<<dim3(8, BATCH / 128), 256, GEMM_DSM>>>(ctxb, 512, wmct, bh2, 512, out_mean, nullptr);

    // z (also fills decoder concat z columns)
    z_kernel<<<BATCH, 256>>>(out_mean, out_lv, eps, out_z, dcat);

    // decoder
    wt_conv<<<dim3(16, 48), 256>>>(d_w1, 1536, dw1t);
    wt_conv<<<dim3(16, 16), 256>>>(d_w2, 512, dw2t);
    conv_h<<<BATCH * 1024 / 4 / 256, 256>>>(tc, BATCH * 1024 / 4, 10, 1023, 1536, 0, dcat);
    conv_h<<<BATCH * 1024 / 4 / 256, 256>>>(tr, BATCH * 1024 / 4, 10, 1023, 1536, 0,
                                            dcat + (size_t)BATCH * 1536);
    gemm_mma<1, 0><<<dim3(4, 2 * BATCH / 128), 256, GEMM_DSM>>>(dcat, 1536, dw1t, d_b1, 512, nullptr, d1);
    gemm_mma<1, 1><<<dim3(4, 2 * BATCH / 128), 256, GEMM_DSM>>>(d1, 512, dw2t, d_b2, 512, d2f, nullptr);
    matvec_kernel<<<2 * BATCH / 8, dim3(32, 8)>>>(d2f, d_w3, d_b3, out_rc);

    (void)in_sizes; (void)n_in; (void)out_size;
}

// round 17
// speedup vs baseline: 1.1334x; 1.1334x over previous
#include <cuda_runtime.h>
#include <cuda_fp16.h>
#include <cstdint>

// ---------------- Problem constants ----------------
#define NCTX   65536
#define BATCH  2048
#define LMAX   48

// ---------------- low-level helpers ----------------
__device__ __forceinline__ uint32_t smem_u32(const void* p) {
    uint32_t a;
    asm("{ .reg .u64 t; cvta.to.shared.u64 t, %1; cvt.u32.u64 %0, t; }" : "=r"(a) : "l"(p));
    return a;
}
__device__ __forceinline__ void cp16(uint32_t s, const void* g) {
    asm volatile("cp.async.cg.shared.global [%0], [%1], 16;" :: "r"(s), "l"(g));
}
__device__ __forceinline__ void cp_commit() {
    asm volatile("cp.async.commit_group;" ::: "memory");
}
__device__ __forceinline__ void cp_wait1() {
    asm volatile("cp.async.wait_group 1;" ::: "memory");
}
__device__ __forceinline__ void cp_wait0() {
    asm volatile("cp.async.wait_group 0;" ::: "memory");
}
__device__ __forceinline__ void ldsm4(uint32_t& r0, uint32_t& r1, uint32_t& r2, uint32_t& r3,
                                      uint32_t addr) {
    asm volatile("ldmatrix.sync.aligned.m8n8.x4.shared.b16 {%0,%1,%2,%3}, [%4];"
                 : "=r"(r0), "=r"(r1), "=r"(r2), "=r"(r3) : "r"(addr));
}
__device__ __forceinline__ void mma16816(float* c, uint32_t a0, uint32_t a1, uint32_t a2,
                                         uint32_t a3, uint32_t b0, uint32_t b1) {
    asm volatile(
        "mma.sync.aligned.m16n8k16.row.col.f32.f16.f16.f32 "
        "{%0,%1,%2,%3}, {%4,%5,%6,%7}, {%8,%9}, {%0,%1,%2,%3};"
        : "+f"(c[0]), "+f"(c[1]), "+f"(c[2]), "+f"(c[3])
        : "r"(a0), "r"(a1), "r"(a2), "r"(a3), "r"(b0), "r"(b1));
}

// ---------------- Scratch (static device globals) ----------------
__device__ __half g_a1[NCTX * 512];
__device__ __half g_a2[NCTX * 512];
__device__ float  g_qpp[NCTX * 512];           // q'' = a2 @ M + r
__device__ __half g_ctx[BATCH * 512];          // attention context vectors
__device__ __half g_dcat[2 * BATCH * 1536];
__device__ __half g_d1[2 * BATCH * 512];
// fp16 transposed weights Wt[n][k]
__device__ __half g_w1t[512 * 2048];
__device__ __half g_w2t[512 * 512];
__device__ __half g_Mt[512 * 512];             // Mt[n][k] = (C1@C2^T)[k][n]
__device__ __half g_wmct[1024 * 512];          // (C3@[wm|wlv])^T blocks
__device__ __half g_dw1t[512 * 1536];
__device__ __half g_dw2t[512 * 512];
// fp32 composition scratch
__device__ float g_C1[512 * 512], g_C2[512 * 512], g_C3[512 * 512];
__device__ float g_bc[1536];                   // bqc | bkc | bvc
__device__ float g_r[512];                     // C2 @ bqc
__device__ float g_bh2[1024];                  // composed head bias
__device__ float g_d2[2 * BATCH * 512];

// ---------------- generic HMMA GEMM (fp16 single-pass, 3-stage) ----------------
// OUTMODE: 0 = fp16 (ldc), 1 = fp32 (ldc), 2 = heads split fp32 (N=1024 -> two blocks)
#define STG_BYTES 20480u
#define GEMM_DSM  (3 * 20480)

template <int ACT, int OUTMODE>
__global__ void __launch_bounds__(256, 2)
gemm_mma(const __half* __restrict__ Ah, int K,
         const __half* __restrict__ Bt,
         const float* __restrict__ bias, int ldc,
         float* __restrict__ outF, __half* __restrict__ outH)
{
    extern __shared__ char dsm[];
    const uint32_t smBase = smem_u32(dsm);

    const int tid = threadIdx.x;
    const int lane = tid & 31;
    const int w = tid >> 5;
    const int warp_m = w >> 2;
    const int warp_n = w & 3;
    const int m0 = blockIdx.y * 128;
    const int n0 = blockIdx.x * 128;

    float c[4][4][4];
#pragma unroll
    for (int mi = 0; mi < 4; mi++)
#pragma unroll
        for (int ni = 0; ni < 4; ni++)
#pragma unroll
            for (int r = 0; r < 4; r++) c[mi][ni][r] = 0.f;

    const int nk = K >> 5;

    auto load_stage = [&](int s) {
        const uint32_t sb = smBase + (uint32_t)(s % 3) * STG_BYTES;
        const int k0 = s << 5;
#pragma unroll
        for (int j = 0; j < 2; j++) {
            int slot = tid + j * 256;
            int row = slot >> 2, k8 = slot & 3;
            uint32_t dst = sb + (uint32_t)row * 80u + (uint32_t)k8 * 16u;
            cp16(dst,           Ah + (size_t)(m0 + row) * K + k0 + k8 * 8);
            cp16(dst + 10240u,  Bt + (size_t)(n0 + row) * K + k0 + k8 * 8);
        }
    };

    load_stage(0); cp_commit();
    load_stage(1); cp_commit();

    const int lr = lane & 15;
    const uint32_t lc16 = (uint32_t)(lane >> 4) * 16u;

    for (int s = 0; s < nk; s++) {
        cp_wait1();
        __syncthreads();
        if (s + 2 < nk) load_stage(s + 2);
        cp_commit();

        const uint32_t sb = smBase + (uint32_t)(s % 3) * STG_BYTES;
#pragma unroll
        for (int h = 0; h < 2; h++) {
            const uint32_t koff = (uint32_t)h * 32u + lc16;
            uint32_t aa[4][4], bb[2][4];
#pragma unroll
            for (int mi = 0; mi < 4; mi++) {
                uint32_t addr = sb + (uint32_t)((warp_m * 64 + mi * 16 + lr) * 80) + koff;
                ldsm4(aa[mi][0], aa[mi][1], aa[mi][2], aa[mi][3], addr);
            }
#pragma unroll
            for (int bt = 0; bt < 2; bt++) {
                uint32_t addr = sb + 10240u + (uint32_t)((warp_n * 32 + bt * 16 + lr) * 80) + koff;
                ldsm4(bb[bt][0], bb[bt][1], bb[bt][2], bb[bt][3], addr);
            }
#pragma unroll
            for (int ni = 0; ni < 4; ni++) {
                const int bt = ni >> 1, sl = ni & 1;
#pragma unroll
                for (int mi = 0; mi < 4; mi++)
                    mma16816(c[mi][ni], aa[mi][0], aa[mi][1], aa[mi][2], aa[mi][3],
                             bb[bt][sl], bb[bt][sl + 2]);
            }
        }
    }

#pragma unroll
    for (int mi = 0; mi < 4; mi++) {
        const int row = m0 + warp_m * 64 + mi * 16 + (lane >> 2);
#pragma unroll
        for (int ni = 0; ni < 4; ni++) {
            const int col = n0 + warp_n * 32 + ni * 8 + (lane & 3) * 2;
            const float b0 = bias[col], b1 = bias[col + 1];
            float v0 = c[mi][ni][0] + b0, v1 = c[mi][ni][1] + b1;
            float v2 = c[mi][ni][2] + b0, v3 = c[mi][ni][3] + b1;
            if (ACT == 1) {
                v0 = v0 > 0.f ? v0 : 0.2f * v0;
                v1 = v1 > 0.f ? v1 : 0.2f * v1;
                v2 = v2 > 0.f ? v2 : 0.2f * v2;
                v3 = v3 > 0.f ? v3 : 0.2f * v3;
            } else if (ACT == 2) {
                v0 = fminf(fmaxf(v0, -1.f), 1.f);
                v1 = fminf(fmaxf(v1, -1.f), 1.f);
                v2 = fminf(fmaxf(v2, -1.f), 1.f);
                v3 = fminf(fmaxf(v3, -1.f), 1.f);
            }
            if (OUTMODE == 1) {
                *(float2*)(outF + (size_t)row * ldc + col)       = make_float2(v0, v1);
                *(float2*)(outF + (size_t)(row + 8) * ldc + col) = make_float2(v2, v3);
            } else if (OUTMODE == 2) {
                size_t base = (size_t)(col >> 9) * ((size_t)BATCH * 512) + (col & 511);
                *(float2*)(outF + base + (size_t)row * 512)       = make_float2(v0, v1);
                *(float2*)(outF + base + (size_t)(row + 8) * 512) = make_float2(v2, v3);
            } else {
                *(__half2*)(outH + (size_t)row * ldc + col) =
                    __halves2half2(__float2half_rn(v0), __float2half_rn(v1));
                *(__half2*)(outH + (size_t)(row + 8) * ldc + col) =
                    __halves2half2(__float2half_rn(v2), __float2half_rn(v3));
            }
        }
    }
}

// ---------------- layer-1 GEMM with fused fp32->fp16 conversion ----------------
#define L1_STG 36864u
#define L1_DSM (2 * 36864)

__global__ void __launch_bounds__(256, 2)
gemm_l1(const float* __restrict__ cc, const float* __restrict__ cr,
        const __half* __restrict__ Bt, const float* __restrict__ bias,
        __half* __restrict__ outH)
{
    extern __shared__ char dsm[];
    const uint32_t smBase = smem_u32(dsm);
    const int K = 2048, nk = 64;

    const int tid = threadIdx.x;
    const int lane = tid & 31;
    const int w = tid >> 5;
    const int warp_m = w >> 2;
    const int warp_n = w & 3;
    const int m0 = blockIdx.y * 128;
    const int n0 = blockIdx.x * 128;

    float c[4][4][4];
#pragma unroll
    for (int mi = 0; mi < 4; mi++)
#pragma unroll
        for (int ni = 0; ni < 4; ni++)
#pragma unroll
            for (int r = 0; r < 4; r++) c[mi][ni][r] = 0.f;

    auto load_stage = [&](int s) {
        const uint32_t sb = smBase + (uint32_t)(s & 1) * L1_STG;
        const int k0 = s << 5;
        const float* A = (k0 < 1024) ? cc : cr;
        const int kc = k0 & 1023;
#pragma unroll
        for (int j = 0; j < 4; j++) {
            int slot = tid + j * 256;
            int row = slot >> 3, c8 = slot & 7;
            cp16(sb + (uint32_t)row * 128u + (uint32_t)c8 * 16u,
                 A + (size_t)(m0 + row) * 1024 + kc + c8 * 4);
        }
#pragma unroll
        for (int j = 0; j < 2; j++) {
            int slot = tid + j * 256;
            int row = slot >> 2, k8 = slot & 3;
            cp16(sb + 26624u + (uint32_t)row * 80u + (uint32_t)k8 * 16u,
                 Bt + (size_t)(n0 + row) * 2048 + k0 + k8 * 8);
        }
    };

    load_stage(0); cp_commit();

    const int lr = lane & 15;
    const uint32_t lc16 = (uint32_t)(lane >> 4) * 16u;

    for (int s = 0; s < nk; s++) {
        cp_wait0();
        __syncthreads();
        if (s + 1 < nk) { load_stage(s + 1); cp_commit(); }

        const uint32_t sb = smBase + (uint32_t)(s & 1) * L1_STG;

#pragma unroll
        for (int j = 0; j < 4; j++) {
            int slot = tid + j * 256;
            int row = slot >> 3, c8 = slot & 7;
            float4 v = *(const float4*)(dsm + (size_t)((s & 1) * L1_STG) + row * 128 + c8 * 16);
            char* hp = dsm + (size_t)((s & 1) * L1_STG) + 16384 + row * 80 + c8 * 8;
            *(__half2*)(hp)     = __halves2half2(__float2half_rn(v.x), __float2half_rn(v.y));
            *(__half2*)(hp + 4) = __halves2half2(__float2half_rn(v.z), __float2half_rn(v.w));
        }
        __syncthreads();

#pragma unroll
        for (int h = 0; h < 2; h++) {
            const uint32_t koff = (uint32_t)h * 32u + lc16;
            uint32_t aa[4][4], bb[2][4];
#pragma unroll
            for (int mi = 0; mi < 4; mi++) {
                uint32_t addr = sb + 16384u + (uint32_t)((warp_m * 64 + mi * 16 + lr) * 80) + koff;
                ldsm4(aa[mi][0], aa[mi][1], aa[mi][2], aa[mi][3], addr);
            }
#pragma unroll
            for (int bt = 0; bt < 2; bt++) {
                uint32_t addr = sb + 26624u + (uint32_t)((warp_n * 32 + bt * 16 + lr) * 80) + koff;
                ldsm4(bb[bt][0], bb[bt][1], bb[bt][2], bb[bt][3], addr);
            }
#pragma unroll
            for (int ni = 0; ni < 4; ni++) {
                const int bt = ni >> 1, sl = ni & 1;
#pragma unroll
                for (int mi = 0; mi < 4; mi++)
                    mma16816(c[mi][ni], aa[mi][0], aa[mi][1], aa[mi][2], aa[mi][3],
                             bb[bt][sl], bb[bt][sl + 2]);
            }
        }
    }

#pragma unroll
    for (int mi = 0; mi < 4; mi++) {
        const int row = m0 + warp_m * 64 + mi * 16 + (lane >> 2);
#pragma unroll
        for (int ni = 0; ni < 4; ni++) {
            const int col = n0 + warp_n * 32 + ni * 8 + (lane & 3) * 2;
            const float b0 = bias[col], b1 = bias[col + 1];
            float v0 = c[mi][ni][0] + b0, v1 = c[mi][ni][1] + b1;
            float v2 = c[mi][ni][2] + b0, v3 = c[mi][ni][3] + b1;
            v0 = v0 > 0.f ? v0 : 0.2f * v0;
            v1 = v1 > 0.f ? v1 : 0.2f * v1;
            v2 = v2 > 0.f ? v2 : 0.2f * v2;
            v3 = v3 > 0.f ? v3 : 0.2f * v3;
            *(__half2*)(outH + (size_t)row * 512 + col) =
                __halves2half2(__float2half_rn(v0), __float2half_rn(v1));
            *(__half2*)(outH + (size_t)(row + 8) * 512 + col) =
                __halves2half2(__float2half_rn(v2), __float2half_rn(v3));
        }
    }
}

// ---------------- fp32 -> fp16 (strided into concat buffer) ----------------
__global__ void __launch_bounds__(256)
conv_h(const float* __restrict__ src, int total4, int kshift, int kmask,
       int dstStride, int dstOff, __half* __restrict__ h)
{
    int i = blockIdx.x * 256 + threadIdx.x;
    if (i >= total4) return;
    int e = i << 2;
    int row = e >> kshift, col = e & kmask;
    float4 v = *(const float4*)(src + e);
    size_t o = (size_t)row * dstStride + dstOff + col;
    __half2* hp = (__half2*)(h + o);
    hp[0] = __halves2half2(__float2half_rn(v.x), __float2half_rn(v.y));
    hp[1] = __halves2half2(__float2half_rn(v.z), __float2half_rn(v.w));
}

// ---------------- weight transpose + fp16: W[K,512] -> Wt[512,K] ----------------
__global__ void __launch_bounds__(256)
wt_conv(const float* __restrict__ W, int K, __half* __restrict__ T)
{
    __shared__ float t[32][33];
    const int nb = blockIdx.x * 32, kb = blockIdx.y * 32;
    const int tx = threadIdx.x & 31, ty = threadIdx.x >> 5;
#pragma unroll
    for (int i = 0; i < 32; i += 8)
        t[ty + i][tx] = W[(size_t)(kb + ty + i) * 512 + nb + tx];
    __syncthreads();
#pragma unroll
    for (int i = 0; i < 32; i += 8)
        T[(size_t)(nb + ty + i) * K + kb + tx] = __float2half_rn(t[tx][ty + i]);
}

// ---------------- batched compose Cz = pe_w3 @ Bz (z = 0,1,2), fp32 out ----------------
__global__ void __launch_bounds__(256)
compose_f32_3(const float* __restrict__ A,
              const float* __restrict__ B0, const float* __restrict__ B1, const float* __restrict__ B2,
              float* __restrict__ C0, float* __restrict__ C1o, float* __restrict__ C2o)
{
    const float* B = blockIdx.z == 0 ? B0 : blockIdx.z == 1 ? B1 : B2;
    float* C = blockIdx.z == 0 ? C0 : blockIdx.z == 1 ? C1o : C2o;
    __shared__ float As[64][17];
    __shared__ float Bs[16][68];
    const int i0 = blockIdx.y * 64, nb0 = blockIdx.x * 64;
    const int tx = threadIdx.x & 15, ty = threadIdx.x >> 4;
    float acc[4][4] = {};
    for (int j0 = 0; j0 < 512; j0 += 16) {
        for (int t = threadIdx.x; t < 1024; t += 256) {
            int r = t >> 4, jj = t & 15;
            As[r][jj] = A[(size_t)(i0 + r) * 512 + j0 + jj];
        }
        for (int t = threadIdx.x; t < 1024; t += 256) {
            int r = t >> 6, nn = t & 63;
            Bs[r][nn] = B[(size_t)(j0 + r) * 512 + nb0 + nn];
        }
        __syncthreads();
#pragma unroll
        for (int jj = 0; jj < 16; jj++) {
            float a[4], b[4];
#pragma unroll
            for (int u = 0; u < 4; u++) a[u] = As[ty * 4 + u][jj];
#pragma unroll
            for (int u = 0; u < 4; u++) b[u] = Bs[jj][tx * 4 + u];
#pragma unroll
            for (int u = 0; u < 4; u++)
#pragma unroll
                for (int v = 0; v < 4; v++) acc[u][v] += a[u] * b[v];
        }
        __syncthreads();
    }
#pragma unroll
    for (int u = 0; u < 4; u++)
#pragma unroll
        for (int v = 0; v < 4; v++)
            C[(size_t)(i0 + ty * 4 + u) * 512 + nb0 + tx * 4 + v] = acc[u][v];
}

// ---------------- compose T[n][k] = sum_j A[k][j]*B[n][j], fp16 out ----------------
__global__ void __launch_bounds__(256)
compose_nt(const float* __restrict__ A, const float* __restrict__ B, __half* __restrict__ T)
{
    __shared__ float As[64][17];
    __shared__ float Bs[64][17];
    const int k0 = blockIdx.y * 64, n0 = blockIdx.x * 64;
    const int tx = threadIdx.x & 15, ty = threadIdx.x >> 4;
    float acc[4][4] = {};
    for (int j0 = 0; j0 < 512; j0 += 16) {
        for (int t = threadIdx.x; t < 1024; t += 256) {
            int r = t >> 4, jj = t & 15;
            As[r][jj] = A[(size_t)(k0 + r) * 512 + j0 + jj];
            Bs[r][jj] = B[(size_t)(n0 + r) * 512 + j0 + jj];
        }
        __syncthreads();
#pragma unroll
        for (int jj = 0; jj < 16; jj++) {
            float a[4], b[4];
#pragma unroll
            for (int u = 0; u < 4; u++) a[u] = As[ty * 4 + u][jj];
#pragma unroll
            for (int u = 0; u < 4; u++) b[u] = Bs[tx * 4 + u][jj];
#pragma unroll
            for (int u = 0; u < 4; u++)
#pragma unroll
                for (int v = 0; v < 4; v++) acc[u][v] += a[u] * b[v];
        }
        __syncthreads();
    }
#pragma unroll
    for (int u = 0; u < 4; u++)
#pragma unroll
        for (int v = 0; v < 4; v++)
            T[(size_t)(n0 + tx * 4 + v) * 512 + k0 + ty * 4 + u] = __float2half_rn(acc[u][v]);
}

// ---------------- batched compose T[z][n][k] = (C3@Bz)[k][n] fp16 (z = 0,1) ----------------
__global__ void __launch_bounds__(256)
compose_w2(const float* __restrict__ A,
           const float* __restrict__ B0, const float* __restrict__ B1, __half* __restrict__ T)
{
    const float* B = blockIdx.z == 0 ? B0 : B1;
    __half* Tz = T + (size_t)blockIdx.z * 512 * 512;
    __shared__ float As[64][17];
    __shared__ float Bs[16][68];
    const int i0 = blockIdx.y * 64, nb0 = blockIdx.x * 64;
    const int tx = threadIdx.x & 15, ty = threadIdx.x >> 4;
    float acc[4][4] = {};
    for (int j0 = 0; j0 < 512; j0 += 16) {
        for (int t = threadIdx.x; t < 1024; t += 256) {
            int r = t >> 4, jj = t & 15;
            As[r][jj] = A[(size_t)(i0 + r) * 512 + j0 + jj];
        }
        for (int t = threadIdx.x; t < 1024; t += 256) {
            int r = t >> 6, nn = t & 63;
            Bs[r][nn] = B[(size_t)(j0 + r) * 512 + nb0 + nn];
        }
        __syncthreads();
#pragma unroll
        for (int jj = 0; jj < 16; jj++) {
            float a[4], b[4];
#pragma unroll
            for (int u = 0; u < 4; u++) a[u] = As[ty * 4 + u][jj];
#pragma unroll
            for (int u = 0; u < 4; u++) b[u] = Bs[jj][tx * 4 + u];
#pragma unroll
            for (int u = 0; u < 4; u++)
#pragma unroll
                for (int v = 0; v < 4; v++) acc[u][v] += a[u] * b[v];
        }
        __syncthreads();
    }
#pragma unroll
    for (int u = 0; u < 4; u++)
#pragma unroll
        for (int v = 0; v < 4; v++) {
            int i = i0 + ty * 4 + u, n = nb0 + tx * 4 + v;
            Tz[(size_t)n * 512 + i] = __float2half_rn(acc[u][v]);
        }
}

// ---------------- composed projection biases bqc|bkc|bvc ----------------
__global__ void __launch_bounds__(512)
compose_bias(const float* __restrict__ b3,
             const float* __restrict__ Bq, const float* __restrict__ Bk, const float* __restrict__ Bv,
             const float* __restrict__ bq, const float* __restrict__ bk, const float* __restrict__ bv,
             float* __restrict__ bc)
{
    const int seg = blockIdx.x, n = threadIdx.x;
    const float* B = seg == 0 ? Bq : seg == 1 ? Bk : Bv;
    const float* bb = seg == 0 ? bq : seg == 1 ? bk : bv;
    float s = bb[n];
    for (int j = 0; j < 512; j++) s += b3[j] * B[(size_t)j * 512 + n];
    bc[seg * 512 + n] = s;
}

// ---------------- r = C2 @ bqc ----------------
__global__ void __launch_bounds__(512)
r_bias(const float* __restrict__ C2, const float* __restrict__ bqc, float* __restrict__ r)
{
    const int n = threadIdx.x;
    float s = 0.f;
    for (int j = 0; j < 512; j++) s += C2[(size_t)n * 512 + j] * bqc[j];
    r[n] = s;
}

// ---------------- head bias: bh2[seg*512+n] = bvc . wh[:,n] + bh[n] ----------------
__global__ void __launch_bounds__(512)
hb_compose(const float* __restrict__ bvc,
           const float* __restrict__ Wm, const float* __restrict__ Wlv,
           const float* __restrict__ bm, const float* __restrict__ blv,
           float* __restrict__ bh2)
{
    const int seg = blockIdx.x, n = threadIdx.x;
    const float* B = seg == 0 ? Wm : Wlv;
    const float* bb = seg == 0 ? bm : blv;
    float s = bb[n];
    for (int j = 0; j < 512; j++) s += bvc[j] * B[(size_t)j * 512 + n];
    bh2[seg * 512 + n] = s;
}

// ---------------- Attention: a2 staged fp16->fp32, float4 scores loop ----------------
#define ATT_DSM (LMAX * 512 * 4)   // 96KB fp32

__global__ void __launch_bounds__(256, 2)
attn_kernel(const float* __restrict__ qpp, const __half* __restrict__ a2,
            const int* __restrict__ sse, __half* __restrict__ ctx)
{
    extern __shared__ float ks[];            // [len][512] fp32 (converted a2)
    __shared__ float scores[LMAX][LMAX];
    __shared__ float colsum[LMAX];

    const int b = blockIdx.x;
    const int tid = threadIdx.x;
    const int warp = tid >> 5, lane = tid & 31;
    const int start = sse[2 * b];
    const int len = sse[2 * b + 1] - start;

    // stage a2 (fp16 -> fp32 once)
    {
        const uint4* g = (const uint4*)(a2 + (size_t)start * 512);
        int tot = len * 64;                  // 16B chunks of 8 halves
        for (int i = tid; i < tot; i += 256) {
            uint4 p = g[i];
            const __half2* h2 = (const __half2*)&p;
            float* dst = ks + (size_t)(i >> 6) * 512 + (i & 63) * 8;
            float2 f0 = __half22float2(h2[0]);
            float2 f1 = __half22float2(h2[1]);
            float2 f2 = __half22float2(h2[2]);
            float2 f3 = __half22float2(h2[3]);
            *(float4*)(dst)     = make_float4(f0.x, f0.y, f1.x, f1.y);
            *(float4*)(dst + 4) = make_float4(f2.x, f2.y, f3.x, f3.y);
        }
    }
    __syncthreads();

    // scores[l][m] = q''_l . a2_m (warp per l, q'' registers, float4 k)
    {
        const float scale = 0.044194173824159216f;
        const float4* k4 = (const float4*)ks;
        for (int l = warp; l < len; l += 8) {
            float4 q[4];
            const float4* qr = (const float4*)(qpp + (size_t)(start + l) * 512) + lane;
#pragma unroll
            for (int i = 0; i < 4; i++) q[i] = __ldg(qr + i * 32);
            for (int m = 0; m < len; m++) {
                const float4* kr = k4 + m * 128 + lane;
                float s = 0.f;
#pragma unroll
                for (int i = 0; i < 4; i++) {
                    float4 kv = kr[i * 32];
                    s += q[i].x * kv.x + q[i].y * kv.y + q[i].z * kv.z + q[i].w * kv.w;
                }
#pragma unroll
                for (int off = 16; off > 0; off >>= 1)
                    s += __shfl_xor_sync(0xffffffffu, s, off);
                if (lane == 0) scores[l][m] = s * scale;
            }
        }
    }
    __syncthreads();

    if (tid < len) {
        float mx = -1e30f;
        for (int m = 0; m < len; m++) mx = fmaxf(mx, scores[tid][m]);
        float sum = 0.f;
        for (int m = 0; m < len; m++) {
            float e = __expf(scores[tid][m] - mx);
            scores[tid][m] = e; sum += e;
        }
        float inv = 1.f / sum;
        for (int m = 0; m < len; m++) scores[tid][m] *= inv;
    }
    __syncthreads();

    if (tid < len) {
        float cs = 0.f;
        for (int l = 0; l < len; l++) cs += scores[l][tid];
        colsum[tid] = cs / (float)len;
    }
    __syncthreads();

    for (int d = tid; d < 512; d += 256) {
        float s = 0.f;
        for (int m = 0; m < len; m++)
            s += colsum[m] * ks[m * 512 + d];
        ctx[(size_t)b * 512 + d] = __float2half_rn(s);
    }
}

// ---------------- z: writes out_z + decoder concat z cols ----------------
__global__ void __launch_bounds__(256)
z_kernel(const float* __restrict__ mean, const float* __restrict__ lv,
         const float* __restrict__ eps, float* __restrict__ zout,
         __half* __restrict__ dcat)
{
    __shared__ float red[256];
    const int b = blockIdx.x, tid = threadIdx.x;
    float zi[2];
    float ss = 0.f;
#pragma unroll
    for (int j = 0; j < 2; j++) {
        int d = tid + 256 * j;
        size_t idx = (size_t)b * 512 + d;
        float z = mean[idx] + __expf(0.5f * lv[idx]) * eps[idx];
        zi[j] = z; ss += z * z;
    }
    red[tid] = ss;
    __syncthreads();
    for (int s = 128; s > 0; s >>= 1) {
        if (tid < s) red[tid] += red[tid + s];
        __syncthreads();
    }
    float denom = fmaxf(sqrtf(red[0]), 1e-12f);
    float fac = 22.627416997969522f / denom;
#pragma unroll
    for (int j = 0; j < 2; j++) {
        int d = tid + 256 * j;
        float z = zi[j] * fac;
        zout[(size_t)b * 512 + d] = z;
        __half h = __float2half_rn(z);
        size_t o0 = (size_t)b * 1536 + 1024 + d;
        dcat[o0] = h;
        dcat[o0 + (size_t)BATCH * 1536] = h;
    }
}

// ---------------- final head matvec (4096 rows -> contiguous out) ----------------
__global__ void __launch_bounds__(256)
matvec_kernel(const float* __restrict__ A, const float* __restrict__ w,
              const float* __restrict__ b, float* __restrict__ out)
{
    const int lane = threadIdx.x;
    const int row = blockIdx.x * 8 + threadIdx.y;
    float s = 0.f;
    for (int k = lane; k < 512; k += 32)
        s += A[(size_t)row * 512 + k] * w[k];
#pragma unroll
    for (int off = 16; off > 0; off >>= 1)
        s += __shfl_xor_sync(0xffffffffu, s, off);
    if (lane == 0) out[row] = s + b[0];
}

// ---------------- host side ----------------
extern "C" void kernel_launch(void* const* d_in, const int* in_sizes, int n_in,
                              void* d_out, int out_size)
{
    const float* tc    = (const float*)d_in[0];
    const float* tr    = (const float*)d_in[1];
    const float* cc    = (const float*)d_in[2];
    const float* cr    = (const float*)d_in[3];
    const float* eps   = (const float*)d_in[4];
    const float* pe_w1 = (const float*)d_in[5];
    const float* pe_b1 = (const float*)d_in[6];
    const float* pe_w2 = (const float*)d_in[7];
    const float* pe_b2 = (const float*)d_in[8];
    const float* pe_w3 = (const float*)d_in[9];
    const float* pe_b3 = (const float*)d_in[10];
    const float* wq    = (const float*)d_in[11];
    const float* bq    = (const float*)d_in[12];
    const float* wk    = (const float*)d_in[13];
    const float* bk    = (const float*)d_in[14];
    const float* wv    = (const float*)d_in[15];
    const float* bv    = (const float*)d_in[16];
    const float* wm    = (const float*)d_in[17];
    const float* bm    = (const float*)d_in[18];
    const float* wlv   = (const float*)d_in[19];
    const float* blv   = (const float*)d_in[20];
    const float* d_w1  = (const float*)d_in[21];
    const float* d_b1  = (const float*)d_in[22];
    const float* d_w2  = (const float*)d_in[23];
    const float* d_b2  = (const float*)d_in[24];
    const float* d_w3  = (const float*)d_in[25];
    const float* d_b3  = (const float*)d_in[26];
    const int*   sse   = (const int*)d_in[27];

    float* out = (float*)d_out;
    float* out_rc   = out;
    float* out_mean = out + 2 * BATCH;
    float* out_lv   = out_mean + BATCH * 512;
    float* out_z    = out_lv + BATCH * 512;

    __half *a1, *a2, *ctxb, *dcat, *d1;
    __half *w1t, *w2t, *Mt, *wmct, *dw1t, *dw2t;
    float *qpp, *C1, *C2, *C3, *bc, *rr, *bh2, *d2f;
    cudaGetSymbolAddress((void**)&a1, g_a1);
    cudaGetSymbolAddress((void**)&a2, g_a2);
    cudaGetSymbolAddress((void**)&ctxb, g_ctx);
    cudaGetSymbolAddress((void**)&dcat, g_dcat);
    cudaGetSymbolAddress((void**)&d1, g_d1);
    cudaGetSymbolAddress((void**)&w1t, g_w1t);
    cudaGetSymbolAddress((void**)&w2t, g_w2t);
    cudaGetSymbolAddress((void**)&Mt, g_Mt);
    cudaGetSymbolAddress((void**)&wmct, g_wmct);
    cudaGetSymbolAddress((void**)&dw1t, g_dw1t);
    cudaGetSymbolAddress((void**)&dw2t, g_dw2t);
    cudaGetSymbolAddress((void**)&qpp, g_qpp);
    cudaGetSymbolAddress((void**)&C1, g_C1);
    cudaGetSymbolAddress((void**)&C2, g_C2);
    cudaGetSymbolAddress((void**)&C3, g_C3);
    cudaGetSymbolAddress((void**)&bc, g_bc);
    cudaGetSymbolAddress((void**)&rr, g_r);
    cudaGetSymbolAddress((void**)&bh2, g_bh2);
    cudaGetSymbolAddress((void**)&d2f, g_d2);

    cudaFuncSetAttribute(gemm_l1, cudaFuncAttributeMaxDynamicSharedMemorySize, L1_DSM);
    cudaFuncSetAttribute(gemm_mma<0, 1>, cudaFuncAttributeMaxDynamicSharedMemorySize, GEMM_DSM);
    cudaFuncSetAttribute(gemm_mma<1, 0>, cudaFuncAttributeMaxDynamicSharedMemorySize, GEMM_DSM);
    cudaFuncSetAttribute(gemm_mma<1, 1>, cudaFuncAttributeMaxDynamicSharedMemorySize, GEMM_DSM);
    cudaFuncSetAttribute(gemm_mma<2, 2>, cudaFuncAttributeMaxDynamicSharedMemorySize, GEMM_DSM);
    cudaFuncSetAttribute(attn_kernel, cudaFuncAttributeMaxDynamicSharedMemorySize, ATT_DSM);

    // encoder layers 1-2
    wt_conv<<<dim3(16, 64), 256>>>(pe_w1, 2048, w1t);
    gemm_l1<<<dim3(4, NCTX / 128), 256, L1_DSM>>>(cc, cr, w1t, pe_b1, a1);
    wt_conv<<<dim3(16, 16), 256>>>(pe_w2, 512, w2t);
    gemm_mma<1, 0><<<dim3(4, NCTX / 128), 256, GEMM_DSM>>>(a1, 512, w2t, pe_b2, 512, nullptr, a2);

    // compositions (batched): C1=pe_w3@wq, C2=pe_w3@wk, C3=pe_w3@wv
    compose_f32_3<<<dim3(8, 8, 3), 256>>>(pe_w3, wq, wk, wv, C1, C2, C3);
    compose_bias<<<3, 512>>>(pe_b3, wq, wk, wv, bq, bk, bv, bc);
    compose_nt<<<dim3(8, 8), 256>>>(C1, C2, Mt);
    r_bias<<<1, 512>>>(C2, bc, rr);

    // q'' = a2 @ M + r (fp32 out)
    gemm_mma<0, 1><<<dim3(4, NCTX / 128), 256, GEMM_DSM>>>(a2, 512, Mt, rr, 512, qpp, nullptr);

    // attention -> ctx (fp16)
    attn_kernel<<<BATCH, 256, ATT_DSM>>>(qpp, a2, sse, ctxb);

    // heads: ctx @ (C3@[wm|wlv]) + composed bias
    compose_w2<<<dim3(8, 8, 2), 256>>>(C3, wm, wlv, wmct);
    hb_compose<<<2, 512>>>(bc + 1024, wm, wlv, bm, blv, bh2);
    gemm_mma<2, 2><<<dim3(8, BATCH / 128), 256, GEMM_DSM>>>(ctxb, 512, wmct, bh2, 512, out_mean, nullptr);

    // z
    z_kernel<<<BATCH, 256>>>(out_mean, out_lv, eps, out_z, dcat);

    // decoder
    wt_conv<<<dim3(16, 48), 256>>>(d_w1, 1536, dw1t);
    wt_conv<<<dim3(16, 16), 256>>>(d_w2, 512, dw2t);
    conv_h<<<BATCH * 1024 / 4 / 256, 256>>>(tc, BATCH * 1024 / 4, 10, 1023, 1536, 0, dcat);
    conv_h<<<BATCH * 1024 / 4 / 256, 256>>>(tr, BATCH * 1024 / 4, 10, 1023, 1536, 0,
                                            dcat + (size_t)BATCH * 1536);
    gemm_mma<1, 0><<<dim3(4, 2 * BATCH / 128), 256, GEMM_DSM>>>(dcat, 1536, dw1t, d_b1, 512, nullptr, d1);
    gemm_mma<1, 1><<<dim3(4, 2 * BATCH / 128), 256, GEMM_DSM>>>(d1, 512, dw2t, d_b2, 512, d2f, nullptr);
    matvec_kernel<<<2 * BATCH / 8, dim3(32, 8)>>>(d2f, d_w3, d_b3, out_rc);

    (void)in_sizes; (void)n_in; (void)out_size;
}